// round 1
// baseline (speedup 1.0000x reference)
#include <cuda_runtime.h>
#include <cuda_bf16.h>
#include <cstdint>

// Problem constants
#define BATCH   2
#define SEQLEN  2048
#define DMODEL  1024
#define DSTATE  16
#define DTRANK  64
#define NROWS   (BATCH * SEQLEN)          // 4096

// ---------------------------------------------------------------------------
// Device scratch (allocation-free: static __device__ globals)
// ---------------------------------------------------------------------------
__device__ float  g_u  [(size_t)NROWS * DMODEL];            // scaled input u (16MB)
__device__ float  g_dp [(size_t)NROWS * DTRANK];            // delta_part (1MB)
__device__ float  g_bc [(size_t)NROWS * DSTATE * 2];        // interleaved (Bp,Cp) (0.5MB)
__device__ float4 g_tri[(size_t)NROWS * DMODEL];            // (delta, delta*u, u*D, 0) (64MB)

// ---------------------------------------------------------------------------
// Kernel 1: u = x * sigmoid(trend);  xz = u @ x_proj_w.T  (N=96)
//   writes g_u, g_dp (cols 0..63), g_bc (cols 64..95 interleaved B/C)
//   BM=32 rows/block, BN=96 (full), BK=32, 128 threads, thread tile 4x6
// ---------------------------------------------------------------------------
__global__ __launch_bounds__(128)
void gemm1_kernel(const float* __restrict__ x,
                  const float* __restrict__ W,       // (96, 1024)
                  const float* __restrict__ te)      // (1024,)
{
    __shared__ float As[32][36];   // [k][row], padded
    __shared__ float Ws[32][97];   // [k][col], padded

    const int tid  = threadIdx.x;          // 0..127
    const int row0 = blockIdx.x * 32;
    const int ty   = tid >> 4;             // 0..7  -> rows ty*4..ty*4+3
    const int tx   = tid & 15;             // 0..15 -> cols tx*6..tx*6+5

    float acc[4][6];
#pragma unroll
    for (int i = 0; i < 4; i++)
#pragma unroll
        for (int j = 0; j < 6; j++) acc[i][j] = 0.f;

    for (int kt = 0; kt < DMODEL; kt += 32) {
        // --- load A tile (32 rows x 32 k), apply channel scale, spill u ---
#pragma unroll
        for (int i = 0; i < 8; i++) {
            int e = i * 128 + tid;
            int k = e & 31;
            int r = e >> 5;
            int gk = kt + k;
            float xv = x[(size_t)(row0 + r) * DMODEL + gk];
            float sg = 1.f / (1.f + __expf(-te[gk]));
            float u  = xv * sg;
            As[k][r] = u;
            g_u[(size_t)(row0 + r) * DMODEL + gk] = u;
        }
        // --- load W tile (96 cols x 32 k) ---
#pragma unroll
        for (int i = 0; i < 24; i++) {
            int e = i * 128 + tid;
            int k = e & 31;
            int c = e >> 5;
            Ws[k][c] = W[(size_t)c * DMODEL + kt + k];
        }
        __syncthreads();

#pragma unroll 8
        for (int k = 0; k < 32; k++) {
            float4 a4 = *(const float4*)&As[k][ty * 4];
            float av[4] = {a4.x, a4.y, a4.z, a4.w};
            float wv[6];
#pragma unroll
            for (int j = 0; j < 6; j++) wv[j] = Ws[k][tx * 6 + j];
#pragma unroll
            for (int i = 0; i < 4; i++)
#pragma unroll
                for (int j = 0; j < 6; j++)
                    acc[i][j] = fmaf(av[i], wv[j], acc[i][j]);
        }
        __syncthreads();
    }

    // --- scatter results: cols <64 -> delta_part; 64..79 -> B; 80..95 -> C ---
#pragma unroll
    for (int i = 0; i < 4; i++) {
        int r = row0 + ty * 4 + i;
#pragma unroll
        for (int j = 0; j < 6; j++) {
            int c = tx * 6 + j;
            float v = acc[i][j];
            if (c < DTRANK) {
                g_dp[(size_t)r * DTRANK + c] = v;
            } else if (c < DTRANK + DSTATE) {
                g_bc[((size_t)r * DSTATE + (c - DTRANK)) * 2 + 0] = v;   // Bp
            } else {
                g_bc[((size_t)r * DSTATE + (c - DTRANK - DSTATE)) * 2 + 1] = v; // Cp
            }
        }
    }
}

// ---------------------------------------------------------------------------
// Kernel 2: delta = softplus(dp @ dt_proj_w.T + dt_proj_b)
//   writes g_tri[(r,d)] = (delta, delta*u, u*D, 0)
//   BM=32, BN=128, K=64 (full), 256 threads, thread tile 2x8
// ---------------------------------------------------------------------------
__global__ __launch_bounds__(256)
void gemm2_kernel(const float* __restrict__ dtw,   // (1024, 64)
                  const float* __restrict__ dtb,   // (1024,)
                  const float* __restrict__ Dp)    // (1024,)
{
    __shared__ float dps[64][36];    // [k][row]
    __shared__ float ws [64][132];   // [k][col]

    const int tid  = threadIdx.x;          // 0..255
    const int row0 = blockIdx.x * 32;
    const int col0 = blockIdx.y * 128;
    const int ty   = tid >> 4;             // 0..15 -> rows ty*2..+1
    const int tx   = tid & 15;             // 0..15 -> cols tx*8..+7

    // load A tile: 32 rows x 64 k
#pragma unroll
    for (int i = 0; i < 8; i++) {
        int e = i * 256 + tid;
        int k = e & 63;
        int r = e >> 6;
        dps[k][r] = g_dp[(size_t)(row0 + r) * DTRANK + k];
    }
    // load W tile: 128 cols x 64 k
#pragma unroll
    for (int i = 0; i < 32; i++) {
        int e = i * 256 + tid;
        int k = e & 63;
        int c = e >> 6;
        ws[k][c] = dtw[(size_t)(col0 + c) * DTRANK + k];
    }
    __syncthreads();

    float acc[2][8];
#pragma unroll
    for (int i = 0; i < 2; i++)
#pragma unroll
        for (int j = 0; j < 8; j++) acc[i][j] = 0.f;

#pragma unroll 8
    for (int k = 0; k < 64; k++) {
        float2 a2 = *(const float2*)&dps[k][ty * 2];
        float4 w0 = *(const float4*)&ws[k][tx * 8];
        float4 w1 = *(const float4*)&ws[k][tx * 8 + 4];
        float av[2] = {a2.x, a2.y};
        float wv[8] = {w0.x, w0.y, w0.z, w0.w, w1.x, w1.y, w1.z, w1.w};
#pragma unroll
        for (int i = 0; i < 2; i++)
#pragma unroll
            for (int j = 0; j < 8; j++)
                acc[i][j] = fmaf(av[i], wv[j], acc[i][j]);
    }

    // epilogue: softplus + pack (delta, delta*u, u*D)
#pragma unroll
    for (int i = 0; i < 2; i++) {
        int r = row0 + ty * 2 + i;
#pragma unroll
        for (int j = 0; j < 8; j++) {
            int c = col0 + tx * 8 + j;
            float v = acc[i][j] + dtb[c];
            // numerically-stable softplus: max(v,0) + log1p(exp(-|v|))
            float delta = fmaxf(v, 0.f) + log1pf(__expf(-fabsf(v)));
            float u  = g_u[(size_t)r * DMODEL + c];
            g_tri[(size_t)r * DMODEL + c] = make_float4(delta, delta * u, u * Dp[c], 0.f);
        }
    }
}

// ---------------------------------------------------------------------------
// Kernel 3: selective scan.
//   thread = (b, d, n): lane%16 = n, each warp handles 2 (b,d) channels.
//   h_t = exp(delta_t * A[d,n]) * h_{t-1} + (delta_t*u_t) * Bp_t[n]
//   y_t = sum_n h_t * Cp_t[n];  out = y + u*D
//   128 threads/block (8 channels), 256 blocks.
// ---------------------------------------------------------------------------
__global__ __launch_bounds__(128)
void scan_kernel(const float* __restrict__ A_log,   // (1024, 16)
                 float* __restrict__ out)           // (B, L, D)
{
    const int tid  = threadIdx.x;
    const int warp = tid >> 5;
    const int g    = (tid >> 4) & 1;
    const int n    = tid & 15;

    const int ch = blockIdx.x * 8 + warp * 2 + g;   // 0..2047
    const int b  = ch >> 10;
    const int d  = ch & 1023;

    // per-thread constant A[d][n] (negative)
    const float A = -__expf(A_log[(size_t)d * DSTATE + n]);

    const float4* __restrict__ tp  = g_tri + (size_t)b * SEQLEN * DMODEL + d;  // stride DMODEL
    const float2* __restrict__ bcp = (const float2*)g_bc + (size_t)b * SEQLEN * DSTATE + n; // stride DSTATE
    float* __restrict__ op = out + (size_t)b * SEQLEN * DMODEL + d;            // stride DMODEL

    const bool writer = (n == 0);
    float h = 0.f;

#pragma unroll 8
    for (int l = 0; l < SEQLEN; l++) {
        float4 t  = tp [(size_t)l * DMODEL];
        float2 cc = bcp[(size_t)l * DSTATE];
        float a = __expf(t.x * A);
        h = fmaf(a, h, t.y * cc.x);
        float y = h * cc.y;
        y += __shfl_xor_sync(0xffffffffu, y, 8);
        y += __shfl_xor_sync(0xffffffffu, y, 4);
        y += __shfl_xor_sync(0xffffffffu, y, 2);
        y += __shfl_xor_sync(0xffffffffu, y, 1);
        if (writer) op[(size_t)l * DMODEL] = y + t.z;
    }
}

// ---------------------------------------------------------------------------
// Launch
// ---------------------------------------------------------------------------
extern "C" void kernel_launch(void* const* d_in, const int* in_sizes, int n_in,
                              void* d_out, int out_size)
{
    const float* x    = (const float*)d_in[0];   // (2, 2048, 1024)
    const float* Alog = (const float*)d_in[1];   // (1024, 16)
    const float* xpw  = (const float*)d_in[2];   // (96, 1024)
    const float* dtw  = (const float*)d_in[3];   // (1024, 64)
    const float* dtb  = (const float*)d_in[4];   // (1024,)
    const float* Dp   = (const float*)d_in[5];   // (1024,)
    const float* te   = (const float*)d_in[6];   // (1024,)
    float* out = (float*)d_out;

    gemm1_kernel<<<NROWS / 32, 128>>>(x, xpw, te);
    gemm2_kernel<<<dim3(NROWS / 32, DMODEL / 128), 256>>>(dtw, dtb, Dp);
    scan_kernel<<<(BATCH * DMODEL) / 8, 128>>>(Alog, out);
}

// round 2
// speedup vs baseline: 3.6461x; 3.6461x over previous
#include <cuda_runtime.h>
#include <cuda_bf16.h>
#include <cstdint>

#define BATCH   2
#define SEQLEN  2048
#define DMODEL  1024
#define DSTATE  16
#define DTRANK  64
#define NROWS   (BATCH * SEQLEN)          // 4096
#define NCHUNK  8
#define CLEN    (SEQLEN / NCHUNK)         // 256
#define NCH     (BATCH * DMODEL)          // 2048 channels
#define NGRP    (NCH * NCHUNK)            // 16384 (channel,chunk) groups

// ---------------------------------------------------------------------------
// Device scratch
// ---------------------------------------------------------------------------
__device__ float  g_wp [96 * DMODEL];                        // W * sig(te)
__device__ float  g_dp [(size_t)NROWS * DTRANK];             // delta_part
__device__ float  g_bp [(size_t)NROWS * DSTATE];             // B plane [b*L+l][n]
__device__ float  g_cp [(size_t)NROWS * DSTATE];             // C plane
__device__ float4 g_tri[(size_t)NCH * SEQLEN];               // [b][d][l] = (delta, delta*u, u*D, 0)
__device__ float  g_hl [(size_t)NGRP * DSTATE];              // chunk-local final states
__device__ float  g_T  [(size_t)NGRP];                       // chunk delta sums
__device__ float  g_hin[(size_t)NGRP * DSTATE];              // chunk incoming states

// ---------------------------------------------------------------------------
// K0: fold sigmoid(trend) into x_proj_w:  wp[c][k] = W[c][k] * sig(te[k])
// ---------------------------------------------------------------------------
__global__ __launch_bounds__(256)
void prep_kernel(const float* __restrict__ W, const float* __restrict__ te)
{
    int idx = blockIdx.x * 256 + threadIdx.x;     // 96*1024 = 98304
    if (idx < 96 * DMODEL) {
        int k = idx & (DMODEL - 1);
        float sg = 1.f / (1.f + __expf(-te[k]));
        g_wp[idx] = W[idx] * sg;
    }
}

// ---------------------------------------------------------------------------
// K1: xz = x @ wp^T   (M=4096, N=96, K=1024)
//   BM=32, BN=96, BK=64, 256 threads, thread tile 2x6.  grid = 128
//   epilogue scatters: cols<64 -> g_dp, 64..79 -> g_bp, 80..95 -> g_cp
// ---------------------------------------------------------------------------
__global__ __launch_bounds__(256)
void gemm1_kernel(const float* __restrict__ x)
{
    __shared__ float As[64][33];
    __shared__ float Ws[64][97];

    const int tid  = threadIdx.x;
    const int row0 = blockIdx.x * 32;
    const int ty   = tid >> 4;         // 0..15 -> rows ty*2..+1
    const int tx   = tid & 15;         // 0..15 -> cols tx*6..+5

    float acc[2][6];
#pragma unroll
    for (int i = 0; i < 2; i++)
#pragma unroll
        for (int j = 0; j < 6; j++) acc[i][j] = 0.f;

    for (int kt = 0; kt < DMODEL; kt += 64) {
        // A tile: 32 rows x 64 k  (512 float4, 2/thread)
#pragma unroll
        for (int i = 0; i < 2; i++) {
            int e  = i * 256 + tid;
            int r  = e >> 4;
            int k4 = e & 15;
            float4 v = *(const float4*)&x[(size_t)(row0 + r) * DMODEL + kt + k4 * 4];
            As[k4 * 4 + 0][r] = v.x;
            As[k4 * 4 + 1][r] = v.y;
            As[k4 * 4 + 2][r] = v.z;
            As[k4 * 4 + 3][r] = v.w;
        }
        // W tile: 96 cols x 64 k  (1536 float4, 6/thread)
#pragma unroll
        for (int i = 0; i < 6; i++) {
            int e  = i * 256 + tid;
            int c  = e >> 4;
            int k4 = e & 15;
            float4 v = *(const float4*)&g_wp[(size_t)c * DMODEL + kt + k4 * 4];
            Ws[k4 * 4 + 0][c] = v.x;
            Ws[k4 * 4 + 1][c] = v.y;
            Ws[k4 * 4 + 2][c] = v.z;
            Ws[k4 * 4 + 3][c] = v.w;
        }
        __syncthreads();

#pragma unroll 16
        for (int k = 0; k < 64; k++) {
            float a0 = As[k][ty * 2 + 0];
            float a1 = As[k][ty * 2 + 1];
            float wv[6];
#pragma unroll
            for (int j = 0; j < 6; j++) wv[j] = Ws[k][tx * 6 + j];
#pragma unroll
            for (int j = 0; j < 6; j++) {
                acc[0][j] = fmaf(a0, wv[j], acc[0][j]);
                acc[1][j] = fmaf(a1, wv[j], acc[1][j]);
            }
        }
        __syncthreads();
    }

#pragma unroll
    for (int i = 0; i < 2; i++) {
        int r = row0 + ty * 2 + i;
#pragma unroll
        for (int j = 0; j < 6; j++) {
            int c = tx * 6 + j;
            float v = acc[i][j];
            if (c < DTRANK)                 g_dp[(size_t)r * DTRANK + c] = v;
            else if (c < DTRANK + DSTATE)   g_bp[(size_t)r * DSTATE + (c - DTRANK)] = v;
            else                            g_cp[(size_t)r * DSTATE + (c - DTRANK - DSTATE)] = v;
        }
    }
}

// ---------------------------------------------------------------------------
// K2: delta = softplus(dp @ dtw^T + dtb); write transposed g_tri[b][d][l]
//   BM=32 (rows=l), BN=128 (cols=d), K=64, 256 threads, tile 2x8. grid (128,8)
// ---------------------------------------------------------------------------
__global__ __launch_bounds__(256)
void gemm2_kernel(const float* __restrict__ x,
                  const float* __restrict__ dtw,   // (1024, 64)
                  const float* __restrict__ dtb,
                  const float* __restrict__ te,
                  const float* __restrict__ Dp)
{
    __shared__ float dps[64][33];
    __shared__ float ws [64][132];

    const int tid  = threadIdx.x;
    const int row0 = blockIdx.x * 32;
    const int col0 = blockIdx.y * 128;
    const int ty   = tid >> 4;
    const int tx   = tid & 15;

    // dp tile: 32 rows x 64 k
#pragma unroll
    for (int i = 0; i < 2; i++) {
        int e  = i * 256 + tid;
        int r  = e >> 4;
        int k4 = e & 15;
        float4 v = *(const float4*)&g_dp[(size_t)(row0 + r) * DTRANK + k4 * 4];
        dps[k4 * 4 + 0][r] = v.x;
        dps[k4 * 4 + 1][r] = v.y;
        dps[k4 * 4 + 2][r] = v.z;
        dps[k4 * 4 + 3][r] = v.w;
    }
    // w tile: 128 cols x 64 k
#pragma unroll
    for (int i = 0; i < 8; i++) {
        int e  = i * 256 + tid;
        int c  = e >> 4;
        int k4 = e & 15;
        float4 v = *(const float4*)&dtw[(size_t)(col0 + c) * DTRANK + k4 * 4];
        ws[k4 * 4 + 0][c] = v.x;
        ws[k4 * 4 + 1][c] = v.y;
        ws[k4 * 4 + 2][c] = v.z;
        ws[k4 * 4 + 3][c] = v.w;
    }
    __syncthreads();

    float acc[2][8];
#pragma unroll
    for (int i = 0; i < 2; i++)
#pragma unroll
        for (int j = 0; j < 8; j++) acc[i][j] = 0.f;

#pragma unroll 16
    for (int k = 0; k < 64; k++) {
        float a0 = dps[k][ty * 2 + 0];
        float a1 = dps[k][ty * 2 + 1];
        float4 w0 = *(const float4*)&ws[k][tx * 8];
        float4 w1 = *(const float4*)&ws[k][tx * 8 + 4];
        float wv[8] = {w0.x, w0.y, w0.z, w0.w, w1.x, w1.y, w1.z, w1.w};
#pragma unroll
        for (int j = 0; j < 8; j++) {
            acc[0][j] = fmaf(a0, wv[j], acc[0][j]);
            acc[1][j] = fmaf(a1, wv[j], acc[1][j]);
        }
    }

    // epilogue: softplus, recompute u = x*sig(te), store transposed
#pragma unroll
    for (int i = 0; i < 2; i++) {
        int r = row0 + ty * 2 + i;
        int b = r >> 11;
        int l = r & (SEQLEN - 1);
        int c0 = col0 + tx * 8;
        float4 x0 = *(const float4*)&x[(size_t)r * DMODEL + c0];
        float4 x1 = *(const float4*)&x[(size_t)r * DMODEL + c0 + 4];
        float xv[8] = {x0.x, x0.y, x0.z, x0.w, x1.x, x1.y, x1.z, x1.w};
#pragma unroll
        for (int j = 0; j < 8; j++) {
            int c = c0 + j;
            float sg = 1.f / (1.f + __expf(-te[c]));
            float u  = xv[j] * sg;
            float v  = acc[i][j] + dtb[c];
            float delta = fmaxf(v, 0.f) + log1pf(__expf(-fabsf(v)));
            g_tri[((size_t)b * DMODEL + c) * SEQLEN + l] =
                make_float4(delta, delta * u, u * Dp[c], 0.f);
        }
    }
}

// ---------------------------------------------------------------------------
// K3 (pass A): per (channel, chunk) local scan from h0=0.
//   thread = (group, n); 16 lanes per group; 256 threads = 16 groups/block.
// ---------------------------------------------------------------------------
__global__ __launch_bounds__(256)
void scanA_kernel(const float* __restrict__ A_log)
{
    const int tid = threadIdx.x;
    const int gid = blockIdx.x * 16 + (tid >> 4);     // 0..16383
    const int n   = tid & 15;
    const int ch  = gid >> 3;                          // b*1024 + d
    const int chunk = gid & 7;
    const int b   = ch >> 10;
    const int d   = ch & (DMODEL - 1);

    const float A = -__expf(A_log[(size_t)d * DSTATE + n]);

    const float4* __restrict__ tp = g_tri + (size_t)ch * SEQLEN + chunk * CLEN;
    const float*  __restrict__ bp = g_bp + ((size_t)b * SEQLEN + chunk * CLEN) * DSTATE + n;

    float h = 0.f, T = 0.f;
#pragma unroll 8
    for (int l = 0; l < CLEN; l++) {
        float4 t = tp[l];
        float  B = bp[(size_t)l * DSTATE];
        h = fmaf(__expf(t.x * A), h, t.y * B);
        T += t.x;
    }
    g_hl[(size_t)gid * DSTATE + n] = h;
    if (n == 0) g_T[gid] = T;
}

// ---------------------------------------------------------------------------
// K4 (pass B): sequential chunk combine per (channel, n).
// ---------------------------------------------------------------------------
__global__ __launch_bounds__(256)
void scanB_kernel(const float* __restrict__ A_log)
{
    const int idx = blockIdx.x * 256 + threadIdx.x;   // 32768
    const int ch  = idx >> 4;
    const int n   = idx & 15;
    const int d   = ch & (DMODEL - 1);

    const float A = -__expf(A_log[(size_t)d * DSTATE + n]);

    float hin = 0.f;
#pragma unroll
    for (int j = 0; j < NCHUNK; j++) {
        size_t g = (size_t)(ch * NCHUNK + j);
        g_hin[g * DSTATE + n] = hin;
        hin = g_hl[g * DSTATE + n] + hin * __expf(g_T[g] * A);
    }
}

// ---------------------------------------------------------------------------
// K5 (pass C): full scan per (channel, chunk) with correct h0, y output.
//   Block: 512 threads = 32 channels (d-consecutive) x 16 n, one (b, chunk).
//   Outputs staged in smem, flushed as coalesced 128B rows.
// ---------------------------------------------------------------------------
__global__ __launch_bounds__(512)
void scanC_kernel(const float* __restrict__ A_log,
                  float* __restrict__ out)
{
    __shared__ float ybuf[32][33];

    const int tid   = threadIdx.x;
    const int blk   = blockIdx.x;                // 512 blocks
    const int b     = blk >> 8;
    const int rem   = blk & 255;
    const int dgrp  = rem >> 3;                  // 0..31
    const int chunk = rem & 7;
    const int ci    = tid >> 4;                  // 0..31
    const int n     = tid & 15;
    const int d     = dgrp * 32 + ci;
    const int ch    = b * DMODEL + d;
    const int gid   = ch * NCHUNK + chunk;

    const float A = -__expf(A_log[(size_t)d * DSTATE + n]);
    float h = g_hin[(size_t)gid * DSTATE + n];

    const float4* __restrict__ tp = g_tri + (size_t)ch * SEQLEN + chunk * CLEN;
    const float*  __restrict__ bp = g_bp + ((size_t)b * SEQLEN + chunk * CLEN) * DSTATE + n;
    const float*  __restrict__ cp = g_cp + ((size_t)b * SEQLEN + chunk * CLEN) * DSTATE + n;

    const size_t outbase = ((size_t)b * SEQLEN + chunk * CLEN) * DMODEL + dgrp * 32;

    for (int lb = 0; lb < CLEN / 32; lb++) {
#pragma unroll 8
        for (int li = 0; li < 32; li++) {
            int l = lb * 32 + li;
            float4 t = tp[l];
            float  B = bp[(size_t)l * DSTATE];
            float  C = cp[(size_t)l * DSTATE];
            h = fmaf(__expf(t.x * A), h, t.y * B);
            float y = h * C;
            y += __shfl_xor_sync(0xffffffffu, y, 8);
            y += __shfl_xor_sync(0xffffffffu, y, 4);
            y += __shfl_xor_sync(0xffffffffu, y, 2);
            y += __shfl_xor_sync(0xffffffffu, y, 1);
            if (n == 0) ybuf[li][ci] = y + t.z;
        }
        __syncthreads();
        // flush 32 l x 32 d floats, coalesced 128B rows
#pragma unroll
        for (int it = 0; it < 2; it++) {
            int e  = it * 512 + tid;
            int li = e >> 5;
            int di = e & 31;
            out[outbase + (size_t)(lb * 32 + li) * DMODEL + di] = ybuf[li][di];
        }
        __syncthreads();
    }
}

// ---------------------------------------------------------------------------
// Launch
// ---------------------------------------------------------------------------
extern "C" void kernel_launch(void* const* d_in, const int* in_sizes, int n_in,
                              void* d_out, int out_size)
{
    const float* x    = (const float*)d_in[0];   // (2, 2048, 1024)
    const float* Alog = (const float*)d_in[1];   // (1024, 16)
    const float* xpw  = (const float*)d_in[2];   // (96, 1024)
    const float* dtw  = (const float*)d_in[3];   // (1024, 64)
    const float* dtb  = (const float*)d_in[4];   // (1024,)
    const float* Dp   = (const float*)d_in[5];   // (1024,)
    const float* te   = (const float*)d_in[6];   // (1024,)
    float* out = (float*)d_out;

    prep_kernel <<<(96 * DMODEL + 255) / 256, 256>>>(xpw, te);
    gemm1_kernel<<<NROWS / 32, 256>>>(x);
    gemm2_kernel<<<dim3(NROWS / 32, DMODEL / 128), 256>>>(x, dtw, dtb, te, Dp);
    scanA_kernel<<<NGRP / 16, 256>>>(Alog);
    scanB_kernel<<<(NCH * DSTATE) / 256, 256>>>(Alog);
    scanC_kernel<<<BATCH * 32 * NCHUNK, 512>>>(Alog, out);
}

// round 3
// speedup vs baseline: 6.2400x; 1.7114x over previous
#include <cuda_runtime.h>
#include <cuda_bf16.h>
#include <cstdint>

#define BATCH   2
#define SEQLEN  2048
#define DMODEL  1024
#define DSTATE  16
#define DTRANK  64
#define NROWS   (BATCH * SEQLEN)          // 4096
#define NCHUNK  32
#define CLEN    (SEQLEN / NCHUNK)         // 64
#define NCH     (BATCH * DMODEL)          // 2048 channels
#define NGRP    (NCH * NCHUNK)            // 65536 (channel,chunk) groups

// ---------------------------------------------------------------------------
// Device scratch
// ---------------------------------------------------------------------------
__device__ float  g_wp [96 * DMODEL];                        // W * sig(te)
__device__ float  g_A  [DMODEL * DSTATE];                    // -exp(A_log)
__device__ float  g_dp [(size_t)NROWS * DTRANK];             // delta_part
__device__ float  g_bp [(size_t)NROWS * DSTATE];             // B plane [b*L+l][n]
__device__ float  g_cp [(size_t)NROWS * DSTATE];             // C plane
__device__ float2 g_dd [(size_t)NROWS * DMODEL];             // [b][l][d] = (delta, delta*u)
__device__ float  g_hl [(size_t)NGRP * DSTATE];              // chunk-local final states
__device__ float  g_T  [(size_t)NGRP];                       // chunk delta sums
__device__ float  g_hin[(size_t)NGRP * DSTATE];              // chunk incoming states

// ---------------------------------------------------------------------------
// K0: fold sigmoid(trend) into x_proj_w; precompute A = -exp(A_log)
// ---------------------------------------------------------------------------
__global__ __launch_bounds__(256)
void prep_kernel(const float* __restrict__ W, const float* __restrict__ te,
                 const float* __restrict__ A_log)
{
    int idx = blockIdx.x * 256 + threadIdx.x;
    if (idx < 96 * DMODEL) {
        int k = idx & (DMODEL - 1);
        float sg = 1.f / (1.f + __expf(-te[k]));
        g_wp[idx] = W[idx] * sg;
    }
    if (idx < DMODEL * DSTATE) {
        g_A[idx] = -__expf(A_log[idx]);
    }
}

// ---------------------------------------------------------------------------
// K1: xz = x @ wp^T   (M=4096, N=96, K=1024)
//   BM=32, BN=96, BK=64, 256 threads, thread tile 2x6.  grid = 128
// ---------------------------------------------------------------------------
__global__ __launch_bounds__(256)
void gemm1_kernel(const float* __restrict__ x)
{
    __shared__ float As[64][33];
    __shared__ float Ws[64][97];

    const int tid  = threadIdx.x;
    const int row0 = blockIdx.x * 32;
    const int ty   = tid >> 4;
    const int tx   = tid & 15;

    float acc[2][6];
#pragma unroll
    for (int i = 0; i < 2; i++)
#pragma unroll
        for (int j = 0; j < 6; j++) acc[i][j] = 0.f;

    for (int kt = 0; kt < DMODEL; kt += 64) {
#pragma unroll
        for (int i = 0; i < 2; i++) {
            int e  = i * 256 + tid;
            int r  = e >> 4;
            int k4 = e & 15;
            float4 v = *(const float4*)&x[(size_t)(row0 + r) * DMODEL + kt + k4 * 4];
            As[k4 * 4 + 0][r] = v.x;
            As[k4 * 4 + 1][r] = v.y;
            As[k4 * 4 + 2][r] = v.z;
            As[k4 * 4 + 3][r] = v.w;
        }
#pragma unroll
        for (int i = 0; i < 6; i++) {
            int e  = i * 256 + tid;
            int c  = e >> 4;
            int k4 = e & 15;
            float4 v = *(const float4*)&g_wp[(size_t)c * DMODEL + kt + k4 * 4];
            Ws[k4 * 4 + 0][c] = v.x;
            Ws[k4 * 4 + 1][c] = v.y;
            Ws[k4 * 4 + 2][c] = v.z;
            Ws[k4 * 4 + 3][c] = v.w;
        }
        __syncthreads();

#pragma unroll 16
        for (int k = 0; k < 64; k++) {
            float a0 = As[k][ty * 2 + 0];
            float a1 = As[k][ty * 2 + 1];
            float wv[6];
#pragma unroll
            for (int j = 0; j < 6; j++) wv[j] = Ws[k][tx * 6 + j];
#pragma unroll
            for (int j = 0; j < 6; j++) {
                acc[0][j] = fmaf(a0, wv[j], acc[0][j]);
                acc[1][j] = fmaf(a1, wv[j], acc[1][j]);
            }
        }
        __syncthreads();
    }

#pragma unroll
    for (int i = 0; i < 2; i++) {
        int r = row0 + ty * 2 + i;
#pragma unroll
        for (int j = 0; j < 6; j++) {
            int c = tx * 6 + j;
            float v = acc[i][j];
            if (c < DTRANK)                 g_dp[(size_t)r * DTRANK + c] = v;
            else if (c < DTRANK + DSTATE)   g_bp[(size_t)r * DSTATE + (c - DTRANK)] = v;
            else                            g_cp[(size_t)r * DSTATE + (c - DTRANK - DSTATE)] = v;
        }
    }
}

// ---------------------------------------------------------------------------
// K2: delta = softplus(dp @ dtw^T + dtb); write g_dd[b][l][d] = (delta, delta*u)
//   BM=32 (rows=l), BN=128 (cols=d), K=64, 256 threads, tile 2x8. grid (128,8)
// ---------------------------------------------------------------------------
__global__ __launch_bounds__(256)
void gemm2_kernel(const float* __restrict__ x,
                  const float* __restrict__ dtw,
                  const float* __restrict__ dtb,
                  const float* __restrict__ te)
{
    __shared__ float dps[64][33];
    __shared__ float ws [64][132];

    const int tid  = threadIdx.x;
    const int row0 = blockIdx.x * 32;
    const int col0 = blockIdx.y * 128;
    const int ty   = tid >> 4;
    const int tx   = tid & 15;

#pragma unroll
    for (int i = 0; i < 2; i++) {
        int e  = i * 256 + tid;
        int r  = e >> 4;
        int k4 = e & 15;
        float4 v = *(const float4*)&g_dp[(size_t)(row0 + r) * DTRANK + k4 * 4];
        dps[k4 * 4 + 0][r] = v.x;
        dps[k4 * 4 + 1][r] = v.y;
        dps[k4 * 4 + 2][r] = v.z;
        dps[k4 * 4 + 3][r] = v.w;
    }
#pragma unroll
    for (int i = 0; i < 8; i++) {
        int e  = i * 256 + tid;
        int c  = e >> 4;
        int k4 = e & 15;
        float4 v = *(const float4*)&dtw[(size_t)(col0 + c) * DTRANK + k4 * 4];
        ws[k4 * 4 + 0][c] = v.x;
        ws[k4 * 4 + 1][c] = v.y;
        ws[k4 * 4 + 2][c] = v.z;
        ws[k4 * 4 + 3][c] = v.w;
    }
    __syncthreads();

    float acc[2][8];
#pragma unroll
    for (int i = 0; i < 2; i++)
#pragma unroll
        for (int j = 0; j < 8; j++) acc[i][j] = 0.f;

#pragma unroll 16
    for (int k = 0; k < 64; k++) {
        float a0 = dps[k][ty * 2 + 0];
        float a1 = dps[k][ty * 2 + 1];
        float4 w0 = *(const float4*)&ws[k][tx * 8];
        float4 w1 = *(const float4*)&ws[k][tx * 8 + 4];
        float wv[8] = {w0.x, w0.y, w0.z, w0.w, w1.x, w1.y, w1.z, w1.w};
#pragma unroll
        for (int j = 0; j < 8; j++) {
            acc[0][j] = fmaf(a0, wv[j], acc[0][j]);
            acc[1][j] = fmaf(a1, wv[j], acc[1][j]);
        }
    }

    // epilogue: softplus, u = x*sig(te); coalesced float4 stores of (delta,du) pairs
#pragma unroll
    for (int i = 0; i < 2; i++) {
        int r  = row0 + ty * 2 + i;
        int c0 = col0 + tx * 8;
        float4 x0 = *(const float4*)&x[(size_t)r * DMODEL + c0];
        float4 x1 = *(const float4*)&x[(size_t)r * DMODEL + c0 + 4];
        float xv[8] = {x0.x, x0.y, x0.z, x0.w, x1.x, x1.y, x1.z, x1.w};
        float dl[8], du[8];
#pragma unroll
        for (int j = 0; j < 8; j++) {
            int c = c0 + j;
            float sg = 1.f / (1.f + __expf(-te[c]));
            float u  = xv[j] * sg;
            float v  = acc[i][j] + dtb[c];
            float delta = fmaxf(v, 0.f) + log1pf(__expf(-fabsf(v)));
            dl[j] = delta;
            du[j] = delta * u;
        }
        float4* dst = (float4*)&g_dd[(size_t)r * DMODEL + c0];
#pragma unroll
        for (int j = 0; j < 4; j++)
            dst[j] = make_float4(dl[2*j], du[2*j], dl[2*j+1], du[2*j+1]);
    }
}

// ---------------------------------------------------------------------------
// K3 (pass A): thread = (b, d, chunk), all 16 states in registers.
//   block 256 threads = 256 consecutive d, one (b, chunk). grid = 2*4*32 = 256
// ---------------------------------------------------------------------------
__global__ __launch_bounds__(256)
void scanA_kernel()
{
    __shared__ float Bs[CLEN][DSTATE];   // 4KB

    const int tid   = threadIdx.x;
    const int blk   = blockIdx.x;
    const int b     = blk >> 7;
    const int rem   = blk & 127;
    const int dgrp  = rem >> 5;
    const int chunk = rem & 31;
    const int d     = dgrp * 256 + tid;
    const int ch    = b * DMODEL + d;
    const int gid   = ch * NCHUNK + chunk;
    const int l0    = chunk * CLEN;

    // B tile load: CLEN*16 floats = 256 float4, 1 per thread, contiguous
    {
        const float4* src = (const float4*)&g_bp[((size_t)b * SEQLEN + l0) * DSTATE];
        ((float4*)Bs)[tid] = src[tid];
    }

    float A[DSTATE];
#pragma unroll
    for (int n = 0; n < DSTATE; n++) A[n] = g_A[(size_t)d * DSTATE + n];
    bool uniform = true;
#pragma unroll
    for (int n = 1; n < DSTATE; n++) uniform &= (A[n] == A[0]);

    float h[DSTATE];
#pragma unroll
    for (int n = 0; n < DSTATE; n++) h[n] = 0.f;
    float T = 0.f;

    const float2* __restrict__ dd = g_dd + ((size_t)b * SEQLEN + l0) * DMODEL + d;
    __syncthreads();

    if (uniform) {
        const float A0 = A[0];
#pragma unroll 4
        for (int l = 0; l < CLEN; l++) {
            float2 t = dd[(size_t)l * DMODEL];
            T += t.x;
            float a = __expf(t.x * A0);
#pragma unroll
            for (int n = 0; n < DSTATE; n++)
                h[n] = fmaf(a, h[n], t.y * Bs[l][n]);
        }
    } else {
#pragma unroll 2
        for (int l = 0; l < CLEN; l++) {
            float2 t = dd[(size_t)l * DMODEL];
            T += t.x;
#pragma unroll
            for (int n = 0; n < DSTATE; n++)
                h[n] = fmaf(__expf(t.x * A[n]), h[n], t.y * Bs[l][n]);
        }
    }

#pragma unroll
    for (int n = 0; n < DSTATE; n++) g_hl[(size_t)gid * DSTATE + n] = h[n];
    g_T[gid] = T;
}

// ---------------------------------------------------------------------------
// K4 (pass B): sequential chunk combine per (channel, n). 32768 threads.
// ---------------------------------------------------------------------------
__global__ __launch_bounds__(256)
void scanB_kernel()
{
    const int idx = blockIdx.x * 256 + threadIdx.x;
    const int ch  = idx >> 4;
    const int n   = idx & 15;
    const int d   = ch & (DMODEL - 1);

    const float A = g_A[(size_t)d * DSTATE + n];

    float hin = 0.f;
#pragma unroll
    for (int j = 0; j < NCHUNK; j++) {
        size_t g = (size_t)ch * NCHUNK + j;
        g_hin[g * DSTATE + n] = hin;
        hin = g_hl[g * DSTATE + n] + hin * __expf(g_T[g] * A);
    }
}

// ---------------------------------------------------------------------------
// K5 (pass C): full re-scan with correct h0; direct coalesced y output.
// ---------------------------------------------------------------------------
__global__ __launch_bounds__(256)
void scanC_kernel(const float* __restrict__ x,
                  const float* __restrict__ te,
                  const float* __restrict__ Dp,
                  float* __restrict__ out)
{
    __shared__ float Bs[CLEN][DSTATE];
    __shared__ float Cs[CLEN][DSTATE];

    const int tid   = threadIdx.x;
    const int blk   = blockIdx.x;
    const int b     = blk >> 7;
    const int rem   = blk & 127;
    const int dgrp  = rem >> 5;
    const int chunk = rem & 31;
    const int d     = dgrp * 256 + tid;
    const int ch    = b * DMODEL + d;
    const int gid   = ch * NCHUNK + chunk;
    const int l0    = chunk * CLEN;

    {
        const float4* sb = (const float4*)&g_bp[((size_t)b * SEQLEN + l0) * DSTATE];
        const float4* sc = (const float4*)&g_cp[((size_t)b * SEQLEN + l0) * DSTATE];
        ((float4*)Bs)[tid] = sb[tid];
        ((float4*)Cs)[tid] = sc[tid];
    }

    float A[DSTATE];
#pragma unroll
    for (int n = 0; n < DSTATE; n++) A[n] = g_A[(size_t)d * DSTATE + n];
    bool uniform = true;
#pragma unroll
    for (int n = 1; n < DSTATE; n++) uniform &= (A[n] == A[0]);

    float h[DSTATE];
#pragma unroll
    for (int n = 0; n < DSTATE; n++) h[n] = g_hin[(size_t)gid * DSTATE + n];

    const float sgD = (1.f / (1.f + __expf(-te[d]))) * Dp[d];

    const float2* __restrict__ dd = g_dd + ((size_t)b * SEQLEN + l0) * DMODEL + d;
    const float*  __restrict__ xp = x    + ((size_t)b * SEQLEN + l0) * DMODEL + d;
    float*        __restrict__ op = out  + ((size_t)b * SEQLEN + l0) * DMODEL + d;
    __syncthreads();

    if (uniform) {
        const float A0 = A[0];
#pragma unroll 4
        for (int l = 0; l < CLEN; l++) {
            float2 t  = dd[(size_t)l * DMODEL];
            float  xv = xp[(size_t)l * DMODEL];
            float  a  = __expf(t.x * A0);
            float  y  = 0.f;
#pragma unroll
            for (int n = 0; n < DSTATE; n++) {
                h[n] = fmaf(a, h[n], t.y * Bs[l][n]);
                y    = fmaf(h[n], Cs[l][n], y);
            }
            op[(size_t)l * DMODEL] = fmaf(xv, sgD, y);
        }
    } else {
#pragma unroll 2
        for (int l = 0; l < CLEN; l++) {
            float2 t  = dd[(size_t)l * DMODEL];
            float  xv = xp[(size_t)l * DMODEL];
            float  y  = 0.f;
#pragma unroll
            for (int n = 0; n < DSTATE; n++) {
                h[n] = fmaf(__expf(t.x * A[n]), h[n], t.y * Bs[l][n]);
                y    = fmaf(h[n], Cs[l][n], y);
            }
            op[(size_t)l * DMODEL] = fmaf(xv, sgD, y);
        }
    }
}

// ---------------------------------------------------------------------------
// Launch
// ---------------------------------------------------------------------------
extern "C" void kernel_launch(void* const* d_in, const int* in_sizes, int n_in,
                              void* d_out, int out_size)
{
    const float* x    = (const float*)d_in[0];
    const float* Alog = (const float*)d_in[1];
    const float* xpw  = (const float*)d_in[2];
    const float* dtw  = (const float*)d_in[3];
    const float* dtb  = (const float*)d_in[4];
    const float* Dp   = (const float*)d_in[5];
    const float* te   = (const float*)d_in[6];
    float* out = (float*)d_out;

    prep_kernel <<<(96 * DMODEL + 255) / 256, 256>>>(xpw, te, Alog);
    gemm1_kernel<<<NROWS / 32, 256>>>(x);
    gemm2_kernel<<<dim3(NROWS / 32, DMODEL / 128), 256>>>(x, dtw, dtb, te);
    scanA_kernel<<<BATCH * 4 * NCHUNK, 256>>>();
    scanB_kernel<<<(NCH * DSTATE) / 256, 256>>>();
    scanC_kernel<<<BATCH * 4 * NCHUNK, 256>>>(x, te, Dp, out);
}